// round 12
// baseline (speedup 1.0000x reference)
#include <cuda_runtime.h>
#include <cuda_fp16.h>
#include <cstdint>
#include <cstddef>

// ---------------- dims ----------------
#define BATCH   256
#define SEQ     512
#define EMBD    100
#define HID     1024
#define THREADS 256
#define GST     34            // gate smem row stride (floats)
#define GGT2    (32*GST)      // per-gate block (1088 floats)
#define GKG2    (4*GGT2)      // per-k-group block (4352 floats)
#define DSMEM   (2*GKG2*4)    // 34816 B gate staging

// ---------------- device scratch (fragment-order images; identical to R11) ----------------
// B (weights): [kc18][n_t32][wn4][j4][pair2][lane32] uint4  (9.4 MB)
__device__ uint4 d_Wb[(size_t)18*32*4*4*2*32];
// A (X):       [t512][mb8][xk4][f4][lane32] uint4           (33.6 MB)
__device__ uint4 d_Xa[(size_t)SEQ*4*2*4*4*32];
// A (H state): [buf2][mb8][hk32][f4][lane32] uint4          (0.5 MB each)
__device__ uint4 d_Ha[2][(size_t)4*2*32*4*32];
__device__ float d_biasp[4096];     // [g][1024]
__device__ unsigned d_barc[8];      // per-mb grid-barrier counters

// ---------------- helpers ----------------
__device__ __forceinline__ float sigf(float x){ return 1.0f/(1.0f + __expf(-x)); }
__device__ __forceinline__ unsigned packh2(float a, float b){
    __half2 h = __floats2half2_rn(a, b);
    return *reinterpret_cast<unsigned*>(&h);
}
__device__ __forceinline__ void mma16(float c[4], unsigned a0, unsigned a1, unsigned a2, unsigned a3,
                                      unsigned b0, unsigned b1){
    asm volatile("mma.sync.aligned.m16n8k16.row.col.f32.f16.f16.f32 "
        "{%0,%1,%2,%3}, {%4,%5,%6,%7}, {%8,%9}, {%0,%1,%2,%3};"
        : "+f"(c[0]), "+f"(c[1]), "+f"(c[2]), "+f"(c[3])
        : "r"(a0), "r"(a1), "r"(a2), "r"(a3), "r"(b0), "r"(b1));
}

// ---------------- setup kernels (identical bake layouts to R11) ----------------
// H0 -> A-frag image (buf 0). u32 i: [mb3b][hk5b][f2b][lane5b][c2b]
__global__ void k_init(const float* __restrict__ H0){
    int i = blockIdx.x*blockDim.x + threadIdx.x;
    if (i < 8) d_barc[i] = 0;
    if (i >= 4*2*32*4*32*4) return;
    int c = i&3, l = (i>>2)&31, f = (i>>7)&3, hk = (i>>9)&31;
    int mb = (i>>14)&7;
    int b = mb*32 + (f>>1)*16 + (c&1)*8 + (l>>2);
    int k = hk*32 + (f&1)*16 + ((c>>1)&1)*8 + (l&3)*2;
    reinterpret_cast<unsigned*>(d_Ha[0])[i] =
        packh2(H0[(size_t)b*HID + k], H0[(size_t)b*HID + k + 1]);
}

// tokens/emb -> X A-frag images. u32 i: [t][mb][xk][f][lane][c]
__global__ void k_embed(const int* __restrict__ tokens, const float* __restrict__ emb){
    int i = blockIdx.x*blockDim.x + threadIdx.x;
    if (i >= SEQ*8*4*4*32*4) return;
    int c = i&3, l = (i>>2)&31, f = (i>>7)&3, xk = (i>>9)&3;
    int mb = (i>>11)&7, t = i>>14;
    int b = mb*32 + (f>>1)*16 + (c&1)*8 + (l>>2);
    int e = xk*32 + (f&1)*16 + ((c>>1)&1)*8 + (l&3)*2;
    float f0 = 0.0f, f1 = 0.0f;
    if (e < EMBD){
        int tok = tokens[b*SEQ + t];
        f0 = emb[(size_t)tok*EMBD + e];
        if (e + 1 < EMBD) f1 = emb[(size_t)tok*EMBD + e + 1];
    }
    reinterpret_cast<unsigned*>(d_Xa)[i] = packh2(f0, f1);
}

// weights -> B-frag image. u32 i: [kc][n_t][wn][j][pair][lane][c]
__global__ void k_weights(
    const float* __restrict__ Wxi, const float* __restrict__ Whi,
    const float* __restrict__ Wxf, const float* __restrict__ Whf,
    const float* __restrict__ Wxo, const float* __restrict__ Who,
    const float* __restrict__ Wxc, const float* __restrict__ Whc)
{
    int i = blockIdx.x*blockDim.x + threadIdx.x;
    if (i >= 18*32*4*4*2*32*4) return;
    int c = i&3, lane = (i>>2)&31, pair = (i>>7)&1, j = (i>>8)&3;
    int wn = (i>>10)&3, n_t = (i>>12)&31, kc = i>>17;
    int n8 = pair*2 + (c>>1), khalf = c&1;
    int k = kc*64 + j*16 + khalf*8 + (lane&3)*2;
    int h = n_t*32 + n8*8 + (lane>>2);
    int g = wn;
    const float* Wh = (g==0)?Whi:(g==1)?Whf:(g==2)?Who:Whc;
    const float* Wx = (g==0)?Wxi:(g==1)?Wxf:(g==2)?Wxo:Wxc;
    float f0 = 0.0f, f1 = 0.0f;
    if (k < 1024)             f0 = Wh[(size_t)k*HID + h];
    else if (k < 1024+EMBD)   f0 = Wx[(size_t)(k-1024)*HID + h];
    int k1 = k + 1;
    if (k1 < 1024)            f1 = Wh[(size_t)k1*HID + h];
    else if (k1 < 1024+EMBD)  f1 = Wx[(size_t)(k1-1024)*HID + h];
    reinterpret_cast<unsigned*>(d_Wb)[i] = packh2(f0, f1);
}

__global__ void k_bias(const float* __restrict__ bi, const float* __restrict__ bf,
                       const float* __restrict__ bo, const float* __restrict__ bc){
    int i = blockIdx.x*blockDim.x + threadIdx.x;
    if (i >= 4096) return;
    int g = i >> 10, h = i & 1023;
    d_biasp[i] = (g==0?bi:g==1?bf:g==2?bo:bc)[h];
}

// ---------------- persistent split-K direct-LDG LSTM scan (2 CTAs/SM) ----------------
__global__ void __launch_bounds__(THREADS,2)
lstm_dg(const float* __restrict__ C0, const float* __restrict__ dw,
        const float* __restrict__ db, float* __restrict__ out)
{
    extern __shared__ float gsm[];     // [2 kg][4 gates][32 rows][GST]
    const int tid  = threadIdx.x;
    const int warp = tid >> 5, lane = tid & 31;
    const int kg   = warp >> 2;        // k-group 0/1 (K halves of 576)
    const int wn   = warp & 3;         // gate / 32-N slice
    const int grp  = lane >> 2, quad = lane & 3;
    const int mb   = blockIdx.x >> 5;  // 32-row block 0..7
    const int n_t  = blockIdx.x & 31;
    const int hc0  = kg*18;            // first half-chunk of this group

    // fragment-stream base pointers
    const uint4* Bb = d_Wb + (size_t)(n_t*4 + wn)*256 + lane;
    const uint4* A0 = d_Ha[0] + (size_t)mb*4096 + lane;
    const uint4* A1 = d_Ha[1] + (size_t)mb*4096 + lane;

    // epilogue ownership: thread -> row b0l, h-pairs hb, hb+1
    const int b0l = tid >> 3;            // row 0..31
    const int hb  = (tid & 7) * 2;       // h-pair base (0..14)
    unsigned woff[2];
    float Cst[2][2];
    #pragma unroll
    for (int u = 0; u < 2; u++){
        int hl = (hb + u)*2;             // h within 32-slice (even)
        int hg = n_t*32 + hl;
        int mi = b0l >> 4, r16 = b0l & 15;
        int ki = hl >> 4, kk = hl & 15, chi = kk >> 3, qd = (kk & 7) >> 1;
        int c = (r16 >> 3) + chi*2;
        int l = (r16 & 7)*4 + qd;
        int f = mi*2 + ki;
        woff[u] = (unsigned)((((mb*32 + (hg >> 5))*4 + f)*32 + l)*4 + c);
        int b = mb*32 + b0l;
        Cst[u][0] = C0[(size_t)b*HID + hg];
        Cst[u][1] = C0[(size_t)b*HID + hg + 1];
    }

    float acc[2][4][4];   // [mi][n8][c]

    for (int t = 0; t < SEQ; ++t){
        const uint4* Ah = (t & 1) ? A1 : A0;
        unsigned* Hn = reinterpret_cast<unsigned*>((t & 1) ? d_Ha[0] : d_Ha[1]);
        const uint4* Xb = d_Xa + (size_t)(t*8 + mb)*512 + lane;

        #pragma unroll
        for (int mi = 0; mi < 2; mi++)
            #pragma unroll
            for (int n8 = 0; n8 < 4; n8++)
                acc[mi][n8][0] = acc[mi][n8][1] = acc[mi][n8][2] = acc[mi][n8][3] = 0.0f;

        // register double-buffered fragment stream over this group's 18 half-chunks
        uint4 av[2][4], bv[2][4];
        {
            const uint4* ap = (hc0 < 32) ? (Ah + hc0*128) : (Xb + (hc0-32)*128);
            av[0][0] = ap[0];  av[0][1] = ap[32]; av[0][2] = ap[64]; av[0][3] = ap[96];
            const uint4* bp = Bb + (size_t)(hc0>>1)*32768 + (hc0&1)*128;
            bv[0][0] = bp[0];  bv[0][1] = bp[32]; bv[0][2] = bp[64]; bv[0][3] = bp[96];
        }

        #pragma unroll 2
        for (int i = 0; i < 18; i++){
            int cb = i & 1, nb = cb ^ 1;
            int hn = hc0 + i + 1;
            if (i + 1 < 18){
                const uint4* ap = (hn < 32) ? (Ah + hn*128) : (Xb + (hn-32)*128);
                av[nb][0] = ap[0];  av[nb][1] = ap[32]; av[nb][2] = ap[64]; av[nb][3] = ap[96];
                const uint4* bp = Bb + (size_t)(hn>>1)*32768 + (hn&1)*128;
                bv[nb][0] = bp[0];  bv[nb][1] = bp[32]; bv[nb][2] = bp[64]; bv[nb][3] = bp[96];
            }
            #pragma unroll
            for (int ki = 0; ki < 2; ki++){
                uint4 b0 = bv[cb][ki*2], b1 = bv[cb][ki*2+1];
                #pragma unroll
                for (int mi = 0; mi < 2; mi++){
                    uint4 a = av[cb][mi*2 + ki];
                    mma16(acc[mi][0], a.x,a.y,a.z,a.w, b0.x, b0.y);
                    mma16(acc[mi][1], a.x,a.y,a.z,a.w, b0.z, b0.w);
                    mma16(acc[mi][2], a.x,a.y,a.z,a.w, b1.x, b1.y);
                    mma16(acc[mi][3], a.x,a.y,a.z,a.w, b1.z, b1.w);
                }
            }
        }

        // stage partial gates: gsm[kg][gate wn][row][h_l]
        {
            float* gb = gsm + kg*GKG2 + wn*GGT2;
            #pragma unroll
            for (int mi = 0; mi < 2; mi++){
                int r0 = mi*16 + grp;
                #pragma unroll
                for (int n8 = 0; n8 < 4; n8++){
                    int nl = n8*8 + quad*2;
                    *reinterpret_cast<float2*>(&gb[r0*GST + nl])
                        = make_float2(acc[mi][n8][0], acc[mi][n8][1]);
                    *reinterpret_cast<float2*>(&gb[(r0+8)*GST + nl])
                        = make_float2(acc[mi][n8][2], acc[mi][n8][3]);
                }
            }
        }
        __syncthreads();

        // cell update: sum the two K-halves + bias; H into next step's frag image
        #pragma unroll
        for (int u = 0; u < 2; u++){
            int hl = (hb + u)*2;
            int hg = n_t*32 + hl;
            float bi0 = d_biasp[hg],        bi1 = d_biasp[hg+1];
            float bf0 = d_biasp[1024+hg],   bf1 = d_biasp[1024+hg+1];
            float bo0 = d_biasp[2048+hg],   bo1 = d_biasp[2048+hg+1];
            float bc0 = d_biasp[3072+hg],   bc1 = d_biasp[3072+hg+1];
            float2 gi0 = *reinterpret_cast<float2*>(&gsm[         b0l*GST + hl]);
            float2 gf0 = *reinterpret_cast<float2*>(&gsm[GGT2   + b0l*GST + hl]);
            float2 go0 = *reinterpret_cast<float2*>(&gsm[2*GGT2 + b0l*GST + hl]);
            float2 gc0 = *reinterpret_cast<float2*>(&gsm[3*GGT2 + b0l*GST + hl]);
            float2 gi1 = *reinterpret_cast<float2*>(&gsm[GKG2          + b0l*GST + hl]);
            float2 gf1 = *reinterpret_cast<float2*>(&gsm[GKG2 + GGT2   + b0l*GST + hl]);
            float2 go1 = *reinterpret_cast<float2*>(&gsm[GKG2 + 2*GGT2 + b0l*GST + hl]);
            float2 gc1 = *reinterpret_cast<float2*>(&gsm[GKG2 + 3*GGT2 + b0l*GST + hl]);
            float vi0 = gi0.x + gi1.x + bi0, vi1 = gi0.y + gi1.y + bi1;
            float vf0 = gf0.x + gf1.x + bf0, vf1 = gf0.y + gf1.y + bf1;
            float vo0 = go0.x + go1.x + bo0, vo1 = go0.y + go1.y + bo1;
            float vc0 = gc0.x + gc1.x + bc0, vc1 = gc0.y + gc1.y + bc1;
            float Cn0 = sigf(vf0)*Cst[u][0] + sigf(vi0)*tanhf(vc0);
            float Cn1 = sigf(vf1)*Cst[u][1] + sigf(vi1)*tanhf(vc1);
            Cst[u][0] = Cn0; Cst[u][1] = Cn1;
            float Hv0 = sigf(vo0)*tanhf(Cn0);
            float Hv1 = sigf(vo1)*tanhf(Cn1);
            Hn[woff[u]] = packh2(Hv0, Hv1);
        }

        // grid barrier (per-mb group of 32 CTAs)
        __threadfence();
        __syncthreads();
        if (tid == 0){
            atomicAdd(&d_barc[mb], 1u);
            unsigned target = (unsigned)(t+1)*32u, v;
            do { asm volatile("ld.acquire.gpu.u32 %0, [%1];" : "=r"(v) : "l"(&d_barc[mb])); }
            while (v < target);
        }
        __syncthreads();
    }

    // ---- dense head: out[256,2] = H_final @ dense_w + dense_b (t=511 wrote buf 0) ----
    if (n_t == 0 && tid < 64){
        int rl = tid >> 1, cx = tid & 1;
        const unsigned* Hf = reinterpret_cast<const unsigned*>(d_Ha[0]);
        float sum = db[cx];
        int mi = rl >> 4, r16 = rl & 15;
        int clo = r16 >> 3, lbase = (r16 & 7)*4;
        for (int h = 0; h < HID; h += 2){
            int hk = h >> 5, h5 = h & 31, ki = h5 >> 4, kk = h5 & 15;
            int chi = kk >> 3, qd = (kk & 7) >> 1;
            int c = clo + chi*2, l = lbase + qd, f = mi*2 + ki;
            unsigned off = (unsigned)((((mb*32 + hk)*4 + f)*32 + l)*4 + c);
            unsigned v = Hf[off];
            __half2 hv = *reinterpret_cast<__half2*>(&v);
            sum += __low2float(hv)*dw[h*2 + cx] + __high2float(hv)*dw[(h+1)*2 + cx];
        }
        out[(mb*32 + rl)*2 + cx] = sum;
    }
}

// ---------------- launcher ----------------
extern "C" void kernel_launch(void* const* d_in, const int* in_sizes, int n_in,
                              void* d_out, int out_size)
{
    const int*   tokens = (const int*)  d_in[0];
    const float* H0     = (const float*)d_in[1];
    const float* C0v    = (const float*)d_in[2];
    const float* Wxi = (const float*)d_in[3],  *Whi = (const float*)d_in[4],  *bi = (const float*)d_in[5];
    const float* Wxf = (const float*)d_in[6],  *Whf = (const float*)d_in[7],  *bf = (const float*)d_in[8];
    const float* Wxo = (const float*)d_in[9],  *Who = (const float*)d_in[10], *bo = (const float*)d_in[11];
    const float* Wxc = (const float*)d_in[12], *Whc = (const float*)d_in[13], *bc = (const float*)d_in[14];
    const float* emb = (const float*)d_in[15];
    const float* dw  = (const float*)d_in[16];
    const float* db  = (const float*)d_in[17];
    float* out = (float*)d_out;

    cudaFuncSetAttribute(lstm_dg, cudaFuncAttributeMaxDynamicSharedMemorySize, DSMEM);

    k_init   <<<(4*2*32*4*32*4 + 255)/256, 256>>>(H0);
    k_embed  <<<(SEQ*8*4*4*32*4 + 255)/256, 256>>>(tokens, emb);
    k_weights<<<(18*32*4*4*2*32*4 + 255)/256, 256>>>(Wxi,Whi, Wxf,Whf, Wxo,Who, Wxc,Whc);
    k_bias   <<<16, 256>>>(bi, bf, bo, bc);
    // 256 CTAs (8 m-groups x 32 n-tiles), 2 CTAs/SM on 148 SMs -> all co-resident
    lstm_dg<<<256, THREADS, DSMEM>>>(C0v, dw, db, out);
}